// round 2
// baseline (speedup 1.0000x reference)
#include <cuda_runtime.h>
#include <math.h>

#define NS 16          // samples per block
#define HDIM 512
#define NTHREADS 256

struct Params {
  const float *tokens;
  const float *ent_W1, *ent_b1, *ent_W2, *ent_b2;
  const float *ent_Wpos, *ent_bpos, *ent_Wc, *ent_bc, *ent_Wv, *ent_bv;
  const float *pad_W1, *pad_b1, *pad_W2, *pad_b2;
  const float *attn_W, *attn_b;
  const float *b_Wpos, *b_bpos, *b_Wc, *b_bc, *b_Wv, *b_bv;
  const float *gs_W, *gs_b;
  float *out;
};

__device__ __forceinline__ float softplusf(float x) {
  // stable softplus, matches jax.nn.softplus to fp32 precision
  return (x > 20.f) ? x : log1pf(expf(x));
}

__global__ void __launch_bounds__(NTHREADS, 2)
spectral_kernel(Params p, int B) {
  extern __shared__ float sm[];
  float* s_tok  = sm;                     // NS*100
  float* s_h1   = s_tok + NS * 100;       // NS*HDIM
  float* s_h2   = s_h1  + NS * HDIM;      // NS*HDIM
  float* s_entH = s_h2  + NS * HDIM;      // NS*3*21
  float* s_padH = s_entH + NS * 63;       // NS*6*22

  const int t  = threadIdx.x;
  const int s0 = blockIdx.x * NS;

  // ---- load token tile ----
  for (int i = t; i < NS * 100; i += NTHREADS)
    s_tok[i] = p.tokens[(size_t)s0 * 100 + i];
  __syncthreads();

  // ---- 9 row-groups: 3 entities (own weights) + 6 pads (shared weights) ----
  for (int g = 0; g < 9; ++g) {
    const float *W1, *b1, *W2, *b2;
    int xrow = g;
    if (g < 3) {
      W1 = p.ent_W1 + g * 10 * HDIM; b1 = p.ent_b1 + g * HDIM;
      W2 = p.ent_W2 + g * HDIM * HDIM; b2 = p.ent_b2 + g * HDIM;
    } else {
      W1 = p.pad_W1; b1 = p.pad_b1; W2 = p.pad_W2; b2 = p.pad_b2;
    }

    // ===== Phase A: h1 = relu(x @ W1 + b1), x is (NS,10) =====
    #pragma unroll
    for (int j = 0; j < 2; ++j) {
      int n = t + 256 * j;
      float w[10];
      #pragma unroll
      for (int k = 0; k < 10; ++k) w[k] = W1[k * HDIM + n];
      float bb = b1[n];
      #pragma unroll
      for (int s = 0; s < NS; ++s) {
        const float* x = s_tok + s * 100 + xrow * 10;
        float acc = bb;
        #pragma unroll
        for (int k = 0; k < 10; ++k) acc = fmaf(x[k], w[k], acc);
        s_h1[s * HDIM + n] = fmaxf(acc, 0.f);
      }
    }
    __syncthreads();

    // ===== Phase B: h2 = relu(h1 @ W2 + b2), the 512x512 hot loop =====
    float acc0[NS], acc1[NS];
    #pragma unroll
    for (int s = 0; s < NS; ++s) { acc0[s] = 0.f; acc1[s] = 0.f; }

    for (int k = 0; k < HDIM; k += 4) {
      float wa[4], wb[4];
      #pragma unroll
      for (int kk = 0; kk < 4; ++kk) {
        wa[kk] = W2[(k + kk) * HDIM + t];
        wb[kk] = W2[(k + kk) * HDIM + t + 256];
      }
      #pragma unroll
      for (int s = 0; s < NS; ++s) {
        float4 av = *reinterpret_cast<const float4*>(s_h1 + s * HDIM + k);
        acc0[s] = fmaf(av.x, wa[0], acc0[s]);
        acc0[s] = fmaf(av.y, wa[1], acc0[s]);
        acc0[s] = fmaf(av.z, wa[2], acc0[s]);
        acc0[s] = fmaf(av.w, wa[3], acc0[s]);
        acc1[s] = fmaf(av.x, wb[0], acc1[s]);
        acc1[s] = fmaf(av.y, wb[1], acc1[s]);
        acc1[s] = fmaf(av.z, wb[2], acc1[s]);
        acc1[s] = fmaf(av.w, wb[3], acc1[s]);
      }
    }
    {
      float b0v = b2[t], b1v = b2[t + 256];
      #pragma unroll
      for (int s = 0; s < NS; ++s) {
        s_h2[s * HDIM + t]       = fmaxf(acc0[s] + b0v, 0.f);
        s_h2[s * HDIM + t + 256] = fmaxf(acc1[s] + b1v, 0.f);
      }
    }
    __syncthreads();

    // ===== Phase C: head projections (linear in h2) =====
    if (g < 3) {
      int e = g;
      for (int idx = t; idx < NS * 21; idx += NTHREADS) {
        int s = idx / 21, c = idx % 21;
        const float* wcol; int stride;
        if (c < 3)       { wcol = p.ent_Wpos + e * HDIM * 3 + c;        stride = 3; }
        else if (c < 12) { wcol = p.ent_Wc   + e * HDIM * 9 + (c - 3);  stride = 9; }
        else             { wcol = p.ent_Wv   + e * HDIM * 9 + (c - 12); stride = 9; }
        float acc = 0.f;
        const float* h2r = s_h2 + s * HDIM;
        #pragma unroll 8
        for (int k = 0; k < HDIM; ++k) acc = fmaf(h2r[k], wcol[k * stride], acc);
        s_entH[s * 63 + e * 21 + c] = acc;
      }
    } else {
      int pd = g - 3;
      // heads are linear, so softmax-weighted agg of hp2 == weighted agg of head outputs
      for (int idx = t; idx < NS * 22; idx += NTHREADS) {
        int s = idx / 22, c = idx % 22;
        const float* wcol; int stride;
        if (c < 3)       { wcol = p.b_Wpos + c;        stride = 3; }
        else if (c < 12) { wcol = p.b_Wc + (c - 3);    stride = 9; }
        else if (c < 21) { wcol = p.b_Wv + (c - 12);   stride = 9; }
        else             { wcol = p.attn_W;            stride = 1; }
        float acc = 0.f;
        const float* h2r = s_h2 + s * HDIM;
        #pragma unroll 8
        for (int k = 0; k < HDIM; ++k) acc = fmaf(h2r[k], wcol[k * stride], acc);
        s_padH[(s * 6 + pd) * 22 + c] = acc;
      }
    }
    __syncthreads();
  }

  // ===== Phase D: per-sample epilogue (one thread per sample) =====
  if (t < NS) {
    int s = t;
    float* o = p.out + (size_t)(s0 + s) * 105;

    // softmax over the 6 pad attention logits
    float lg[6];
    float m = -1e30f;
    float attnb = p.attn_b[0];
    #pragma unroll
    for (int pd = 0; pd < 6; ++pd) {
      lg[pd] = s_padH[(s * 6 + pd) * 22 + 21] + attnb;
      m = fmaxf(m, lg[pd]);
    }
    float den = 0.f;
    #pragma unroll
    for (int pd = 0; pd < 6; ++pd) { lg[pd] = expf(lg[pd] - m); den += lg[pd]; }
    float inv = 1.f / den;

    float agg[21];
    #pragma unroll
    for (int c = 0; c < 21; ++c) agg[c] = 0.f;
    #pragma unroll
    for (int pd = 0; pd < 6; ++pd) {
      float w = lg[pd] * inv;
      #pragma unroll
      for (int c = 0; c < 21; ++c)
        agg[c] = fmaf(w, s_padH[(s * 6 + pd) * 22 + c], agg[c]);
    }

    float pos[4][3], coef[4][9], cov[4][9];
    for (int e = 0; e < 3; ++e) {
      const float* eh = s_entH + s * 63 + e * 21;
      for (int d = 0; d < 3; ++d) pos[e][d]  = eh[d]      + p.ent_bpos[e * 3 + d];
      for (int c = 0; c < 9; ++c) coef[e][c] = eh[3 + c]  + p.ent_bc[e * 9 + c];
      for (int c = 0; c < 9; ++c) cov[e][c]  = softplusf(eh[12 + c] + p.ent_bv[e * 9 + c]);
    }
    for (int d = 0; d < 3; ++d) pos[3][d]  = agg[d]      + p.b_bpos[d];
    for (int c = 0; c < 9; ++c) coef[3][c] = agg[3 + c]  + p.b_bc[c];
    for (int c = 0; c < 9; ++c) cov[3][c]  = softplusf(agg[12 + c] + p.b_bv[c]);

    // field_flat: per entity i -> [coef(9), cov(9), wall(6)]
    for (int i = 0; i < 4; ++i) {
      float x = pos[i][0], y = pos[i][1], z = pos[i][2];
      float wf[6];
      wf[0] = (4096.f - x) / 1000.f;
      wf[1] = (4096.f + x) / 1000.f;
      wf[2] = (5120.f - y) / 1000.f;
      wf[3] = (5120.f + y) / 1000.f;
      wf[4] = (z - 0.f) / 1000.f;
      wf[5] = (2044.f - z) / 1000.f;
      for (int c = 0; c < 9; ++c) o[i * 24 + c]      = coef[i][c];
      for (int c = 0; c < 9; ++c) o[i * 24 + 9 + c]  = cov[i][c];
      for (int c = 0; c < 6; ++c) o[i * 24 + 18 + c] = wf[c];
    }

    // tri: upper triangle of I = exp(-d2/(2*sigma^2)) * (coef_i . coef_j)/tau
    const int iu[6] = {0, 0, 0, 1, 1, 2};
    const int ju[6] = {1, 2, 3, 2, 3, 3};
    for (int q = 0; q < 6; ++q) {
      int i = iu[q], j = ju[q];
      float d2 = 0.f;
      for (int d = 0; d < 3; ++d) {
        float df = pos[i][d] - pos[j][d];
        d2 = fmaf(df, df, d2);
      }
      float cd = 0.f;
      for (int c = 0; c < 9; ++c) cd = fmaf(coef[i][c], coef[j][c], cd);
      o[96 + q] = expf(-2.f * d2) * cd;   // 2*sigma^2 = 0.5 ; tau = 1
    }

    // game: tokens row 9 @ gs_W + gs_b
    for (int d = 0; d < 3; ++d) {
      float gacc = p.gs_b[d];
      for (int k = 0; k < 10; ++k)
        gacc = fmaf(s_tok[s * 100 + 90 + k], p.gs_W[k * 3 + d], gacc);
      o[102 + d] = gacc;
    }
  }
}

extern "C" void kernel_launch(void* const* d_in, const int* in_sizes, int n_in,
                              void* d_out, int out_size) {
  Params p;
  p.tokens   = (const float*)d_in[0];
  p.ent_W1   = (const float*)d_in[1];
  p.ent_b1   = (const float*)d_in[2];
  p.ent_W2   = (const float*)d_in[3];
  p.ent_b2   = (const float*)d_in[4];
  p.ent_Wpos = (const float*)d_in[5];
  p.ent_bpos = (const float*)d_in[6];
  p.ent_Wc   = (const float*)d_in[7];
  p.ent_bc   = (const float*)d_in[8];
  p.ent_Wv   = (const float*)d_in[9];
  p.ent_bv   = (const float*)d_in[10];
  p.pad_W1   = (const float*)d_in[11];
  p.pad_b1   = (const float*)d_in[12];
  p.pad_W2   = (const float*)d_in[13];
  p.pad_b2   = (const float*)d_in[14];
  p.attn_W   = (const float*)d_in[15];
  p.attn_b   = (const float*)d_in[16];
  p.b_Wpos   = (const float*)d_in[17];
  p.b_bpos   = (const float*)d_in[18];
  p.b_Wc     = (const float*)d_in[19];
  p.b_bc     = (const float*)d_in[20];
  p.b_Wv     = (const float*)d_in[21];
  p.b_bv     = (const float*)d_in[22];
  p.gs_W     = (const float*)d_in[23];
  p.gs_b     = (const float*)d_in[24];
  p.out      = (float*)d_out;

  int B = in_sizes[0] / 100;      // tokens is (B,10,10)
  int blocks = B / NS;            // B=32768 -> 2048 blocks

  size_t smem = (size_t)(NS * 100 + 2 * NS * HDIM + NS * 63 + NS * 132) * sizeof(float);
  cudaFuncSetAttribute(spectral_kernel, cudaFuncAttributeMaxDynamicSharedMemorySize,
                       (int)smem);
  spectral_kernel<<<blocks, NTHREADS, smem>>>(p, B);
}

// round 4
// speedup vs baseline: 5.4000x; 5.4000x over previous
#include <cuda_runtime.h>
#include <cuda_fp16.h>
#include <math.h>
#include <stdint.h>

// ---------------- packed fp16 weights in device globals ----------------
// g_w2: [m4][kc16][n512][k32]  (B n-major per k32 chunk)  = 1,048,576 halves
// g_w1: [m4][n512][k16]        (k10 = b1, k11..15 = 0)    = 32,768 halves
// g_hd: [m4][n32][k512]        (n: 0-2 pos, 3-11 c, 12-20 v, 21 attn) = 65,536
__device__ __align__(16) __half g_w2[1048576];
__device__ __align__(16) __half g_w1[32768];
__device__ __align__(16) __half g_hd[65536];

struct P2 {
  const float *tokens;
  const float *ent_bpos, *ent_bc, *ent_bv, *ent_b2;
  const float *pad_b2;
  const float *b_bpos, *b_bc, *b_bv;
  const float *gs_W, *gs_b;
  float *out;
};

__global__ void pack_kernel(const float* eW2, const float* pW2,
                            const float* eW1, const float* eb1,
                            const float* pW1, const float* pb1,
                            const float* eWpos, const float* eWc, const float* eWv,
                            const float* bWpos, const float* bWc, const float* bWv,
                            const float* attnW) {
  int tid = blockIdx.x * blockDim.x + threadIdx.x;
  int NT = gridDim.x * blockDim.x;
  for (int idx = tid; idx < 4 * 512 * 512; idx += NT) {
    int m = idx >> 18, r = idx & 262143, k = r >> 9, n = r & 511;
    float v = (m < 3) ? eW2[m * 262144 + k * 512 + n] : pW2[k * 512 + n];
    g_w2[((m * 16 + (k >> 5)) * 512 + n) * 32 + (k & 31)] = __float2half(v);
  }
  for (int idx = tid; idx < 4 * 512 * 16; idx += NT) {
    int m = idx >> 13, r = idx & 8191, n = r >> 4, k = r & 15;
    float v = 0.f;
    if (k < 10)       v = (m < 3) ? eW1[m * 5120 + k * 512 + n] : pW1[k * 512 + n];
    else if (k == 10) v = (m < 3) ? eb1[m * 512 + n] : pb1[n];
    g_w1[(m * 512 + n) * 16 + k] = __float2half(v);
  }
  for (int idx = tid; idx < 4 * 32 * 512; idx += NT) {
    int m = idx >> 14, r = idx & 16383, n = r >> 9, k = r & 511;
    float v = 0.f;
    if (m < 3) {
      if (n < 3)       v = eWpos[m * 1536 + k * 3 + n];
      else if (n < 12) v = eWc[m * 4608 + k * 9 + (n - 3)];
      else if (n < 21) v = eWv[m * 4608 + k * 9 + (n - 12)];
    } else {
      if (n < 3)       v = bWpos[k * 3 + n];
      else if (n < 12) v = bWc[k * 9 + (n - 3)];
      else if (n < 21) v = bWv[k * 9 + (n - 12)];
      else if (n == 21) v = attnW[k];
    }
    g_hd[(m * 32 + n) * 512 + k] = __float2half(v);
  }
}

// ---------------- mma helpers ----------------
__device__ __forceinline__ void ldsm4(uint32_t a, uint32_t& r0, uint32_t& r1,
                                      uint32_t& r2, uint32_t& r3) {
  asm volatile("ldmatrix.sync.aligned.m8n8.x4.shared.b16 {%0,%1,%2,%3}, [%4];"
               : "=r"(r0), "=r"(r1), "=r"(r2), "=r"(r3) : "r"(a));
}
__device__ __forceinline__ void ldsm2(uint32_t a, uint32_t& r0, uint32_t& r1) {
  asm volatile("ldmatrix.sync.aligned.m8n8.x2.shared.b16 {%0,%1}, [%2];"
               : "=r"(r0), "=r"(r1) : "r"(a));
}
__device__ __forceinline__ void mma16816(float* c, uint32_t a0, uint32_t a1,
                                         uint32_t a2, uint32_t a3,
                                         uint32_t b0, uint32_t b1) {
  asm volatile(
      "mma.sync.aligned.m16n8k16.row.col.f32.f16.f16.f32 "
      "{%0,%1,%2,%3},{%4,%5,%6,%7},{%8,%9},{%0,%1,%2,%3};"
      : "+f"(c[0]), "+f"(c[1]), "+f"(c[2]), "+f"(c[3])
      : "r"(a0), "r"(a1), "r"(a2), "r"(a3), "r"(b0), "r"(b1));
}
#define CP16(dst, src) asm volatile("cp.async.ca.shared.global [%0], [%1], 16;" :: "r"(dst), "l"(src))
#define CPCOMMIT() asm volatile("cp.async.commit_group;" ::: "memory")
#define CPWAIT0() asm volatile("cp.async.wait_group 0;" ::: "memory")

// ---------------- smem layout (bytes) ----------------
#define NTH 256
static constexpr int SA  = 520;  // fp16 stride for A / H2 tiles (64 x 512)
static constexpr int SB  = 40;   // fp16 stride for W2 k32 chunks (512 rows)
static constexpr int SW1 = 24;   // fp16 stride for W1 / x-tile
static constexpr int SH  = 520;  // fp16 stride for heads B (32 rows x 512)
static constexpr int OF_A   = 0;                     // 66,560
static constexpr int OF_H2  = 66560;                 // 66,560
static constexpr int OF_B0  = 133120;                // 40,960
static constexpr int OF_B1  = 174080;                // 40,960 (also x-tile)
static constexpr int OF_XT  = OF_B1;
static constexpr int OF_ENT = 215040;                // 3*64*22 fp16 = 8,448
static constexpr int OF_PAD = 223488;                // 64*22 fp16  = 2,816
static constexpr int OF_AGG = 226304;                // 64*23 f32   = 5,888
static constexpr int SMEM_SZ = 232192;

__device__ __forceinline__ float softplusf(float x) { return (x > 20.f) ? x : log1pf(expf(x)); }

__global__ void __launch_bounds__(NTH, 1) spectral_mma_kernel(P2 p) {
  extern __shared__ __align__(128) unsigned char sm[];
  const uint32_t smb = (uint32_t)__cvta_generic_to_shared(sm);
  const int t = threadIdx.x, wid = t >> 5, lane = t & 31;
  const int s0 = blockIdx.x * 64;
  const int r = wid & 3, nh = wid >> 2;        // warp tile: rows r*16.., cols nh*256..
  const int grp = lane >> 3, rin = lane & 7;   // ldmatrix x4 addressing
  const int l2 = lane & 15, grp2 = l2 >> 3, rin2 = l2 & 7;  // ldmatrix x2
  const int lr = lane >> 2, lc2 = (lane & 3) * 2;           // C frag mapping

  // init online-softmax state
  if (t < 64) {
    float* ag = (float*)(sm + OF_AGG) + t * 23;
#pragma unroll
    for (int c = 0; c < 21; ++c) ag[c] = 0.f;
    ag[21] = -1e30f; ag[22] = 0.f;
  }
  __syncthreads();

  float acc[32][4];
  float hacc[4][4];

  for (int g = 0; g < 9; ++g) {
    const int m = (g < 3) ? g : 3;

    // ---- build x-tile (64x16, ones col at k=10) + copy W1 B ----
    for (int i = t; i < 64 * 16; i += NTH) {
      int s = i >> 4, k = i & 15;
      float v = (k < 10) ? p.tokens[(size_t)(s0 + s) * 100 + g * 10 + k] : (k == 10 ? 1.f : 0.f);
      *(__half*)(sm + OF_XT + (s * SW1 + k) * 2) = __float2half(v);
    }
    for (int u = t; u < 1024; u += NTH)
      *(uint4*)(sm + OF_B0 + (u >> 1) * 48 + (u & 1) * 16) =
          *(const uint4*)((const char*)g_w1 + m * 16384 + u * 16);
    __syncthreads();

    // ---- phase A: h1 = relu(x @ W1T), k=16, 32 n-tiles per warp ----
#pragma unroll
    for (int nt = 0; nt < 32; ++nt)
#pragma unroll
      for (int i = 0; i < 4; ++i) acc[nt][i] = 0.f;
    {
      uint32_t a0, a1, a2, a3;
      int arow = r * 16 + (grp & 1) * 8 + rin, akoff = (grp >> 1) * 8;
      ldsm4(smb + OF_XT + (arow * SW1 + akoff) * 2, a0, a1, a2, a3);
#pragma unroll
      for (int nt = 0; nt < 32; ++nt) {
        uint32_t b0, b1;
        int brow = nh * 256 + nt * 8 + rin2;
        ldsm2(smb + OF_B0 + (brow * SW1 + grp2 * 8) * 2, b0, b1);
        mma16816(acc[nt], a0, a1, a2, a3, b0, b1);
      }
    }
#pragma unroll
    for (int nt = 0; nt < 32; ++nt) {
      int col = nh * 256 + nt * 8 + lc2;
      int row0 = r * 16 + lr;
      *(__half2*)(sm + OF_A + (row0 * SA + col) * 2) =
          __floats2half2_rn(fmaxf(acc[nt][0], 0.f), fmaxf(acc[nt][1], 0.f));
      *(__half2*)(sm + OF_A + ((row0 + 8) * SA + col) * 2) =
          __floats2half2_rn(fmaxf(acc[nt][2], 0.f), fmaxf(acc[nt][3], 0.f));
    }
    __syncthreads();

    // ---- GEMM1: h2 = relu(h1 @ W2T + b2), 16 k32 chunks, cp.async 2-buf ----
#pragma unroll
    for (int nt = 0; nt < 32; ++nt)
#pragma unroll
      for (int i = 0; i < 4; ++i) acc[nt][i] = 0.f;
    const char* w2base = (const char*)g_w2 + m * 524288;
    // prefetch chunk 0 -> buf0
    for (int u = t; u < 2048; u += NTH)
      CP16(smb + OF_B0 + (u >> 2) * 80 + (u & 3) * 16, w2base + u * 16);
    CPCOMMIT();
    for (int kc = 0; kc < 16; ++kc) {
      CPWAIT0();
      __syncthreads();
      if (kc < 15) {
        uint32_t bo = ((kc + 1) & 1) ? OF_B1 : OF_B0;
        const char* src = w2base + (kc + 1) * 32768;
        for (int u = t; u < 2048; u += NTH)
          CP16(smb + bo + (u >> 2) * 80 + (u & 3) * 16, src + u * 16);
        CPCOMMIT();
      }
      uint32_t bo = (kc & 1) ? OF_B1 : OF_B0;
#pragma unroll
      for (int kt = 0; kt < 2; ++kt) {
        uint32_t a0, a1, a2, a3;
        int arow = r * 16 + (grp & 1) * 8 + rin;
        int ak = kc * 32 + kt * 16 + (grp >> 1) * 8;
        ldsm4(smb + OF_A + (arow * SA + ak) * 2, a0, a1, a2, a3);
#pragma unroll
        for (int nt = 0; nt < 32; ++nt) {
          uint32_t b0, b1;
          int brow = nh * 256 + nt * 8 + rin2;
          ldsm2(smb + bo + (brow * SB + kt * 16 + grp2 * 8) * 2, b0, b1);
          mma16816(acc[nt], a0, a1, a2, a3, b0, b1);
        }
      }
    }
    const float* b2 = (g < 3) ? (p.ent_b2 + m * 512) : p.pad_b2;
#pragma unroll
    for (int nt = 0; nt < 32; ++nt) {
      int col = nh * 256 + nt * 8 + lc2;
      float bb0 = __ldg(b2 + col), bb1 = __ldg(b2 + col + 1);
      int row0 = r * 16 + lr;
      *(__half2*)(sm + OF_H2 + (row0 * SA + col) * 2) =
          __floats2half2_rn(fmaxf(acc[nt][0] + bb0, 0.f), fmaxf(acc[nt][1] + bb1, 0.f));
      *(__half2*)(sm + OF_H2 + ((row0 + 8) * SA + col) * 2) =
          __floats2half2_rn(fmaxf(acc[nt][2] + bb0, 0.f), fmaxf(acc[nt][3] + bb1, 0.f));
    }
    __syncthreads();

    // ---- heads: copy B (32x512) then 64x32x512 mma on warps 0-3 ----
    for (int u = t; u < 2048; u += NTH)
      *(uint4*)(sm + OF_B0 + (u >> 6) * 1040 + (u & 63) * 16) =
          *(const uint4*)((const char*)g_hd + m * 32768 + u * 16);
    __syncthreads();
    if (wid < 4) {
#pragma unroll
      for (int nt = 0; nt < 4; ++nt)
#pragma unroll
        for (int i = 0; i < 4; ++i) hacc[nt][i] = 0.f;
      for (int kt = 0; kt < 32; ++kt) {
        uint32_t a0, a1, a2, a3;
        int arow = wid * 16 + (grp & 1) * 8 + rin;
        int ak = kt * 16 + (grp >> 1) * 8;
        ldsm4(smb + OF_H2 + (arow * SA + ak) * 2, a0, a1, a2, a3);
#pragma unroll
        for (int nt = 0; nt < 4; ++nt) {
          uint32_t b0, b1;
          int brow = nt * 8 + rin2;
          ldsm2(smb + OF_B0 + (brow * SH + kt * 16 + grp2 * 8) * 2, b0, b1);
          mma16816(hacc[nt], a0, a1, a2, a3, b0, b1);
        }
      }
      int dstb = (g < 3) ? (OF_ENT + g * 64 * 44) : OF_PAD;
#pragma unroll
      for (int nt = 0; nt < 4; ++nt) {
        int col = nt * 8 + lc2;
        if (col < 22) {
          int row0 = wid * 16 + lr;
          *(__half2*)(sm + dstb + row0 * 44 + col * 2) =
              __floats2half2_rn(hacc[nt][0], hacc[nt][1]);
          *(__half2*)(sm + dstb + (row0 + 8) * 44 + col * 2) =
              __floats2half2_rn(hacc[nt][2], hacc[nt][3]);
        }
      }
    }
    __syncthreads();

    // ---- pad groups: online softmax fold (threads 0..63) ----
    if (g >= 3 && t < 64) {
      const __half* ps = (const __half*)(sm + OF_PAD) + t * 22;
      float* ag = (float*)(sm + OF_AGG) + t * 23;
      float l = __half2float(ps[21]);
      float mo = ag[21], d = ag[22];
      float mn = fmaxf(mo, l);
      float sc = expf(mo - mn), w = expf(l - mn);
      ag[22] = d * sc + w;
      ag[21] = mn;
#pragma unroll
      for (int c = 0; c < 21; ++c) ag[c] = ag[c] * sc + w * __half2float(ps[c]);
    }
    __syncthreads();
  }

  // ---- epilogue: one thread per sample ----
  if (t < 64) {
    int s = t;
    float* o = p.out + (size_t)(s0 + s) * 105;
    const float* ag = (const float*)(sm + OF_AGG) + s * 23;
    float inv = 1.f / ag[22];
    float pos[4][3], coef[4][9], cov[4][9];
    for (int e = 0; e < 3; ++e) {
      const __half* eh = (const __half*)(sm + OF_ENT) + (e * 64 + s) * 22;
      for (int d = 0; d < 3; ++d) pos[e][d]  = __half2float(eh[d]) + p.ent_bpos[e * 3 + d];
      for (int c = 0; c < 9; ++c) coef[e][c] = __half2float(eh[3 + c]) + p.ent_bc[e * 9 + c];
      for (int c = 0; c < 9; ++c) cov[e][c]  = softplusf(__half2float(eh[12 + c]) + p.ent_bv[e * 9 + c]);
    }
    for (int d = 0; d < 3; ++d) pos[3][d]  = ag[d] * inv + p.b_bpos[d];
    for (int c = 0; c < 9; ++c) coef[3][c] = ag[3 + c] * inv + p.b_bc[c];
    for (int c = 0; c < 9; ++c) cov[3][c]  = softplusf(ag[12 + c] * inv + p.b_bv[c]);
    for (int i = 0; i < 4; ++i) {
      float x = pos[i][0], y = pos[i][1], z = pos[i][2];
      for (int c = 0; c < 9; ++c) o[i * 24 + c]     = coef[i][c];
      for (int c = 0; c < 9; ++c) o[i * 24 + 9 + c] = cov[i][c];
      o[i * 24 + 18] = (4096.f - x) * 1e-3f;
      o[i * 24 + 19] = (4096.f + x) * 1e-3f;
      o[i * 24 + 20] = (5120.f - y) * 1e-3f;
      o[i * 24 + 21] = (5120.f + y) * 1e-3f;
      o[i * 24 + 22] = z * 1e-3f;
      o[i * 24 + 23] = (2044.f - z) * 1e-3f;
    }
    const int iu[6] = {0, 0, 0, 1, 1, 2}, ju[6] = {1, 2, 3, 2, 3, 3};
    for (int q = 0; q < 6; ++q) {
      int i = iu[q], j = ju[q];
      float d2 = 0.f, cd = 0.f;
      for (int d = 0; d < 3; ++d) { float df = pos[i][d] - pos[j][d]; d2 = fmaf(df, df, d2); }
      for (int c = 0; c < 9; ++c) cd = fmaf(coef[i][c], coef[j][c], cd);
      o[96 + q] = expf(-2.f * d2) * cd;
    }
    for (int d = 0; d < 3; ++d) {
      float ga = p.gs_b[d];
      for (int k = 0; k < 10; ++k)
        ga = fmaf(p.tokens[(size_t)(s0 + s) * 100 + 90 + k], p.gs_W[k * 3 + d], ga);
      o[102 + d] = ga;
    }
  }
}

extern "C" void kernel_launch(void* const* d_in, const int* in_sizes, int n_in,
                              void* d_out, int out_size) {
  pack_kernel<<<512, 256>>>(
      (const float*)d_in[3],  (const float*)d_in[13],
      (const float*)d_in[1],  (const float*)d_in[2],
      (const float*)d_in[11], (const float*)d_in[12],
      (const float*)d_in[5],  (const float*)d_in[7],  (const float*)d_in[9],
      (const float*)d_in[17], (const float*)d_in[19], (const float*)d_in[21],
      (const float*)d_in[15]);
  P2 p;
  p.tokens = (const float*)d_in[0];
  p.ent_bpos = (const float*)d_in[6];
  p.ent_bc = (const float*)d_in[8];
  p.ent_bv = (const float*)d_in[10];
  p.ent_b2 = (const float*)d_in[4];
  p.pad_b2 = (const float*)d_in[14];
  p.b_bpos = (const float*)d_in[18];
  p.b_bc = (const float*)d_in[20];
  p.b_bv = (const float*)d_in[22];
  p.gs_W = (const float*)d_in[23];
  p.gs_b = (const float*)d_in[24];
  p.out = (float*)d_out;

  int B = in_sizes[0] / 100;
  cudaFuncSetAttribute(spectral_mma_kernel, cudaFuncAttributeMaxDynamicSharedMemorySize, SMEM_SZ);
  spectral_mma_kernel<<<B / 64, NTH, SMEM_SZ>>>(p);
}

// round 5
// speedup vs baseline: 8.1314x; 1.5058x over previous
#include <cuda_runtime.h>
#include <cuda_fp16.h>
#include <math.h>
#include <stdint.h>

// ---------------- packed fp16 weights ----------------
// g_w2: [m4][nh2][kc16][n256][k32]   = 1,048,576 halves (2MB)
// g_w1: [m4][n512][k16]  (k10 = b1)  = 32,768 halves
// g_hd: [m4][n32][k512]  (n: 0-2 pos, 3-11 coef, 12-20 cov, 21 attn)
__device__ __align__(16) __half g_w2[1048576];
__device__ __align__(16) __half g_w1[32768];
__device__ __align__(16) __half g_hd[65536];
// head partials: [g*2+nh (18)][sample (32768)][22] f32
__device__ float g_part[18 * 32768 * 22];

struct PM {
  const float *tokens;
  const float *ent_b2, *pad_b2;
  float *out;
};
struct PE {
  const float *tokens;
  const float *ent_bpos, *ent_bc, *ent_bv;
  const float *b_bpos, *b_bc, *b_bv;
  const float *gs_W, *gs_b;
  float *out;
};

__global__ void pack_kernel(const float* eW2, const float* pW2,
                            const float* eW1, const float* eb1,
                            const float* pW1, const float* pb1,
                            const float* eWpos, const float* eWc, const float* eWv,
                            const float* bWpos, const float* bWc, const float* bWv,
                            const float* attnW) {
  int tid = blockIdx.x * blockDim.x + threadIdx.x;
  int NT = gridDim.x * blockDim.x;
  for (int idx = tid; idx < 4 * 512 * 512; idx += NT) {
    int m = idx >> 18, r = idx & 262143, k = r >> 9, n = r & 511;
    float v = (m < 3) ? eW2[m * 262144 + k * 512 + n] : pW2[k * 512 + n];
    int dst = ((m * 2 + (n >> 8)) * 16 + (k >> 5)) * 8192 + (n & 255) * 32 + (k & 31);
    g_w2[dst] = __float2half(v);
  }
  for (int idx = tid; idx < 4 * 512 * 16; idx += NT) {
    int m = idx >> 13, r = idx & 8191, n = r >> 4, k = r & 15;
    float v = 0.f;
    if (k < 10)       v = (m < 3) ? eW1[m * 5120 + k * 512 + n] : pW1[k * 512 + n];
    else if (k == 10) v = (m < 3) ? eb1[m * 512 + n] : pb1[n];
    g_w1[(m * 512 + n) * 16 + k] = __float2half(v);
  }
  for (int idx = tid; idx < 4 * 32 * 512; idx += NT) {
    int m = idx >> 14, r = idx & 16383, n = r >> 9, k = r & 511;
    float v = 0.f;
    if (m < 3) {
      if (n < 3)       v = eWpos[m * 1536 + k * 3 + n];
      else if (n < 12) v = eWc[m * 4608 + k * 9 + (n - 3)];
      else if (n < 21) v = eWv[m * 4608 + k * 9 + (n - 12)];
    } else {
      if (n < 3)       v = bWpos[k * 3 + n];
      else if (n < 12) v = bWc[k * 9 + (n - 3)];
      else if (n < 21) v = bWv[k * 9 + (n - 12)];
      else if (n == 21) v = attnW[k];
    }
    g_hd[(m * 32 + n) * 512 + k] = __float2half(v);
  }
}

// ---------------- mma helpers ----------------
__device__ __forceinline__ void ldsm4(uint32_t a, uint32_t& r0, uint32_t& r1,
                                      uint32_t& r2, uint32_t& r3) {
  asm volatile("ldmatrix.sync.aligned.m8n8.x4.shared.b16 {%0,%1,%2,%3}, [%4];"
               : "=r"(r0), "=r"(r1), "=r"(r2), "=r"(r3) : "r"(a));
}
__device__ __forceinline__ void mma16816(float* c, uint32_t a0, uint32_t a1,
                                         uint32_t a2, uint32_t a3,
                                         uint32_t b0, uint32_t b1) {
  asm volatile(
      "mma.sync.aligned.m16n8k16.row.col.f32.f16.f16.f32 "
      "{%0,%1,%2,%3},{%4,%5,%6,%7},{%8,%9},{%0,%1,%2,%3};"
      : "+f"(c[0]), "+f"(c[1]), "+f"(c[2]), "+f"(c[3])
      : "r"(a0), "r"(a1), "r"(a2), "r"(a3), "r"(b0), "r"(b1));
}
#define CP16(dst, src) asm volatile("cp.async.ca.shared.global [%0], [%1], 16;" :: "r"(dst), "l"(src))
#define CPCOMMIT() asm volatile("cp.async.commit_group;" ::: "memory")
#define CPWAIT0() asm volatile("cp.async.wait_group 0;" ::: "memory")

// ---------------- smem layout (bytes) ----------------
#define NTH 256
static constexpr int OF_A  = 0;       // A/h1/h2 tile: 64 rows x 1040B (520 halves)
static constexpr int OF_B0 = 66560;   // 20,480 (256 rows x 80B) ; W1 (512x48B) spans B0+B1
static constexpr int OF_B1 = 87040;   // 20,480 ; heads B (32x528B) at OF_B0
static constexpr int OF_XT = 91136;   // x-tile 64 x 48B = 3072
static constexpr int SMEM_SZ = 107520;

__device__ __forceinline__ float softplusf(float x) { return (x > 20.f) ? x : log1pf(expf(x)); }

__global__ void __launch_bounds__(NTH, 2) spectral_mma_kernel(PM p) {
  extern __shared__ __align__(128) unsigned char sm[];
  const uint32_t smb = (uint32_t)__cvta_generic_to_shared(sm);
  const int t = threadIdx.x, wid = t >> 5, lane = t & 31;
  const int sblk = blockIdx.x, rem = blockIdx.y;
  const int g = rem >> 1, nh = rem & 1;
  const int m = (g < 3) ? g : 3;
  const int s0 = sblk * 64;
  const int mw = wid & 1, nw = wid >> 1;           // 2 M-warps x 4 N-warps (64 x 256)
  // ldmatrix lane addressing
  const int ag_r = ((lane >> 3) & 1) * 8 + (lane & 7);  // A: row offset
  const int ag_k = ((lane >> 4) & 1) * 8;               // A: k offset
  const int bg_n = ((lane >> 4) & 1) * 8 + (lane & 7);  // B: n offset
  const int bg_k = ((lane >> 3) & 1) * 8;               // B: k offset
  const int lr = lane >> 2, lc2 = (lane & 3) * 2;       // C frag mapping

  float acc[2][8][4];

  // ---- build x-tile (64x16, ones at k=10) ----
  for (int i = t; i < 64 * 16; i += NTH) {
    int s = i >> 4, k = i & 15;
    float v = (k < 10) ? p.tokens[(size_t)(s0 + s) * 100 + g * 10 + k] : (k == 10 ? 1.f : 0.f);
    *(__half*)(sm + OF_XT + s * 48 + k * 2) = __float2half(v);
  }
  // ---- copy full W1 (512 x 16 halves), stride 48B ----
  for (int u = t; u < 1024; u += NTH)
    *(uint4*)(sm + OF_B0 + (u >> 1) * 48 + (u & 1) * 16) =
        *(const uint4*)((const char*)g_w1 + m * 16384 + u * 16);
  __syncthreads();

  // ---- phase A: h1 = relu(x @ W1T) -> A-tile fp16, two 256-col passes ----
  for (int pss = 0; pss < 2; ++pss) {
#pragma unroll
    for (int mt = 0; mt < 2; ++mt)
#pragma unroll
      for (int nt = 0; nt < 8; ++nt)
#pragma unroll
        for (int i = 0; i < 4; ++i) acc[mt][nt][i] = 0.f;
    uint32_t A0[4], A1[4];
    ldsm4(smb + OF_XT + (mw * 32 + ag_r) * 48 + ag_k * 2, A0[0], A0[1], A0[2], A0[3]);
    ldsm4(smb + OF_XT + (mw * 32 + 16 + ag_r) * 48 + ag_k * 2, A1[0], A1[1], A1[2], A1[3]);
#pragma unroll
    for (int pnt = 0; pnt < 4; ++pnt) {
      uint32_t b[4];
      int nr = pss * 256 + nw * 64 + pnt * 16 + bg_n;
      ldsm4(smb + OF_B0 + nr * 48 + bg_k * 2, b[0], b[1], b[2], b[3]);
      mma16816(acc[0][pnt * 2],     A0[0], A0[1], A0[2], A0[3], b[0], b[1]);
      mma16816(acc[0][pnt * 2 + 1], A0[0], A0[1], A0[2], A0[3], b[2], b[3]);
      mma16816(acc[1][pnt * 2],     A1[0], A1[1], A1[2], A1[3], b[0], b[1]);
      mma16816(acc[1][pnt * 2 + 1], A1[0], A1[1], A1[2], A1[3], b[2], b[3]);
    }
#pragma unroll
    for (int mt = 0; mt < 2; ++mt)
#pragma unroll
      for (int nt = 0; nt < 8; ++nt) {
        int col = pss * 256 + nw * 64 + nt * 8 + lc2;
        int row0 = mw * 32 + mt * 16 + lr;
        *(__half2*)(sm + OF_A + row0 * 1040 + col * 2) =
            __floats2half2_rn(fmaxf(acc[mt][nt][0], 0.f), fmaxf(acc[mt][nt][1], 0.f));
        *(__half2*)(sm + OF_A + (row0 + 8) * 1040 + col * 2) =
            __floats2half2_rn(fmaxf(acc[mt][nt][2], 0.f), fmaxf(acc[mt][nt][3], 0.f));
      }
  }
  __syncthreads();

  // ---- GEMM1: h2_half = relu(h1 @ W2T[nh] + b2), 16 k32 chunks, cp.async 2-buf ----
#pragma unroll
  for (int mt = 0; mt < 2; ++mt)
#pragma unroll
    for (int nt = 0; nt < 8; ++nt)
#pragma unroll
      for (int i = 0; i < 4; ++i) acc[mt][nt][i] = 0.f;
  const char* w2base = (const char*)g_w2 + ((size_t)(m * 2 + nh) * 16) * 16384;
  for (int u = t; u < 1024; u += NTH)                       // prefetch chunk 0
    CP16(smb + OF_B0 + (u >> 2) * 80 + (u & 3) * 16, w2base + u * 16);
  CPCOMMIT();
  for (int kc = 0; kc < 16; ++kc) {
    CPWAIT0();
    __syncthreads();
    if (kc < 15) {
      uint32_t bo = ((kc + 1) & 1) ? OF_B1 : OF_B0;
      const char* src = w2base + (size_t)(kc + 1) * 16384;
      for (int u = t; u < 1024; u += NTH)
        CP16(smb + bo + (u >> 2) * 80 + (u & 3) * 16, src + u * 16);
      CPCOMMIT();
    }
    uint32_t bo = (kc & 1) ? OF_B1 : OF_B0;
#pragma unroll
    for (int kt = 0; kt < 2; ++kt) {
      int ak = kc * 32 + kt * 16;
      uint32_t A0[4], A1[4];
      ldsm4(smb + OF_A + (mw * 32 + ag_r) * 1040 + (ak + ag_k) * 2, A0[0], A0[1], A0[2], A0[3]);
      ldsm4(smb + OF_A + (mw * 32 + 16 + ag_r) * 1040 + (ak + ag_k) * 2, A1[0], A1[1], A1[2], A1[3]);
#pragma unroll
      for (int pnt = 0; pnt < 4; ++pnt) {
        uint32_t b[4];
        int nr = nw * 64 + pnt * 16 + bg_n;
        ldsm4(smb + bo + nr * 80 + (kt * 16 + bg_k) * 2, b[0], b[1], b[2], b[3]);
        mma16816(acc[0][pnt * 2],     A0[0], A0[1], A0[2], A0[3], b[0], b[1]);
        mma16816(acc[0][pnt * 2 + 1], A0[0], A0[1], A0[2], A0[3], b[2], b[3]);
        mma16816(acc[1][pnt * 2],     A1[0], A1[1], A1[2], A1[3], b[0], b[1]);
        mma16816(acc[1][pnt * 2 + 1], A1[0], A1[1], A1[2], A1[3], b[2], b[3]);
      }
    }
  }
  // h2 (bias+relu, fp16) written in place over A-tile cols 0..255
  {
    const float* b2 = (g < 3) ? (p.ent_b2 + m * 512) : p.pad_b2;
#pragma unroll
    for (int mt = 0; mt < 2; ++mt)
#pragma unroll
      for (int nt = 0; nt < 8; ++nt) {
        int lcol = nw * 64 + nt * 8 + lc2;
        float bb0 = __ldg(b2 + nh * 256 + lcol), bb1 = __ldg(b2 + nh * 256 + lcol + 1);
        int row0 = mw * 32 + mt * 16 + lr;
        *(__half2*)(sm + OF_A + row0 * 1040 + lcol * 2) =
            __floats2half2_rn(fmaxf(acc[mt][nt][0] + bb0, 0.f), fmaxf(acc[mt][nt][1] + bb1, 0.f));
        *(__half2*)(sm + OF_A + (row0 + 8) * 1040 + lcol * 2) =
            __floats2half2_rn(fmaxf(acc[mt][nt][2] + bb0, 0.f), fmaxf(acc[mt][nt][3] + bb1, 0.f));
      }
  }
  __syncthreads();

  // ---- heads B copy: 32 n rows x 256 k halves (k slice nh*256..), stride 528B ----
  for (int u = t; u < 1024; u += NTH) {
    int n = u >> 5, kq = u & 31;
    *(uint4*)(sm + OF_B0 + n * 528 + kq * 16) =
        *(const uint4*)(g_hd + ((m * 32 + n) * 512 + nh * 256 + kq * 8));
  }
  __syncthreads();

  // ---- heads GEMM (warps 0-3): 64x32 over k=256, partials -> g_part ----
  if (wid < 4) {
    float hacc[4][4];
#pragma unroll
    for (int nt = 0; nt < 4; ++nt)
#pragma unroll
      for (int i = 0; i < 4; ++i) hacc[nt][i] = 0.f;
    for (int kt = 0; kt < 16; ++kt) {
      uint32_t A0[4];
      ldsm4(smb + OF_A + (wid * 16 + ag_r) * 1040 + (kt * 16 + ag_k) * 2,
            A0[0], A0[1], A0[2], A0[3]);
#pragma unroll
      for (int pnt = 0; pnt < 2; ++pnt) {
        uint32_t b[4];
        ldsm4(smb + OF_B0 + (pnt * 16 + bg_n) * 528 + (kt * 16 + bg_k) * 2,
              b[0], b[1], b[2], b[3]);
        mma16816(hacc[pnt * 2],     A0[0], A0[1], A0[2], A0[3], b[0], b[1]);
        mma16816(hacc[pnt * 2 + 1], A0[0], A0[1], A0[2], A0[3], b[2], b[3]);
      }
    }
#pragma unroll
    for (int nt = 0; nt < 4; ++nt) {
      int col = nt * 8 + lc2;
      if (col < 22) {
        size_t base = ((size_t)(g * 2 + nh) * 32768 + s0 + wid * 16 + lr) * 22 + col;
        g_part[base]             = hacc[nt][0];
        g_part[base + 1]         = hacc[nt][1];
        g_part[base + 8 * 22]    = hacc[nt][2];
        g_part[base + 8 * 22 + 1]= hacc[nt][3];
      }
    }
  }
}

__global__ void epilogue_kernel(PE p, int B) {
  int s = blockIdx.x * blockDim.x + threadIdx.x;
  if (s >= B) return;
  float hd[9][22];
#pragma unroll
  for (int q = 0; q < 9; ++q) {
    const float* p0 = g_part + ((size_t)(q * 2) * 32768 + s) * 22;
    const float* p1 = g_part + ((size_t)(q * 2 + 1) * 32768 + s) * 22;
#pragma unroll
    for (int c = 0; c < 22; ++c) hd[q][c] = p0[c] + p1[c];
  }
  // pad softmax over groups 3..8 (attn col 21; attn_b shift-invariant)
  float mx = -1e30f;
#pragma unroll
  for (int q = 3; q < 9; ++q) mx = fmaxf(mx, hd[q][21]);
  float den = 0.f, agg[21];
#pragma unroll
  for (int c = 0; c < 21; ++c) agg[c] = 0.f;
#pragma unroll
  for (int q = 3; q < 9; ++q) {
    float w = expf(hd[q][21] - mx);
    den += w;
#pragma unroll
    for (int c = 0; c < 21; ++c) agg[c] = fmaf(w, hd[q][c], agg[c]);
  }
  float inv = 1.f / den;

  float* o = p.out + (size_t)s * 105;
  float pos[4][3], coef[4][9], cov[4][9];
  for (int e = 0; e < 3; ++e) {
    for (int d = 0; d < 3; ++d) pos[e][d]  = hd[e][d] + p.ent_bpos[e * 3 + d];
    for (int c = 0; c < 9; ++c) coef[e][c] = hd[e][3 + c] + p.ent_bc[e * 9 + c];
    for (int c = 0; c < 9; ++c) cov[e][c]  = softplusf(hd[e][12 + c] + p.ent_bv[e * 9 + c]);
  }
  for (int d = 0; d < 3; ++d) pos[3][d]  = agg[d] * inv + p.b_bpos[d];
  for (int c = 0; c < 9; ++c) coef[3][c] = agg[3 + c] * inv + p.b_bc[c];
  for (int c = 0; c < 9; ++c) cov[3][c]  = softplusf(agg[12 + c] * inv + p.b_bv[c]);
  for (int i = 0; i < 4; ++i) {
    float x = pos[i][0], y = pos[i][1], z = pos[i][2];
    for (int c = 0; c < 9; ++c) o[i * 24 + c]     = coef[i][c];
    for (int c = 0; c < 9; ++c) o[i * 24 + 9 + c] = cov[i][c];
    o[i * 24 + 18] = (4096.f - x) * 1e-3f;
    o[i * 24 + 19] = (4096.f + x) * 1e-3f;
    o[i * 24 + 20] = (5120.f - y) * 1e-3f;
    o[i * 24 + 21] = (5120.f + y) * 1e-3f;
    o[i * 24 + 22] = z * 1e-3f;
    o[i * 24 + 23] = (2044.f - z) * 1e-3f;
  }
  const int iu[6] = {0, 0, 0, 1, 1, 2}, ju[6] = {1, 2, 3, 2, 3, 3};
  for (int q = 0; q < 6; ++q) {
    int i = iu[q], j = ju[q];
    float d2 = 0.f, cd = 0.f;
    for (int d = 0; d < 3; ++d) { float df = pos[i][d] - pos[j][d]; d2 = fmaf(df, df, d2); }
    for (int c = 0; c < 9; ++c) cd = fmaf(coef[i][c], coef[j][c], cd);
    o[96 + q] = expf(-2.f * d2) * cd;
  }
  for (int d = 0; d < 3; ++d) {
    float ga = p.gs_b[d];
    for (int k = 0; k < 10; ++k)
      ga = fmaf(p.tokens[(size_t)s * 100 + 90 + k], p.gs_W[k * 3 + d], ga);
    o[102 + d] = ga;
  }
}

extern "C" void kernel_launch(void* const* d_in, const int* in_sizes, int n_in,
                              void* d_out, int out_size) {
  pack_kernel<<<512, 256>>>(
      (const float*)d_in[3],  (const float*)d_in[13],
      (const float*)d_in[1],  (const float*)d_in[2],
      (const float*)d_in[11], (const float*)d_in[12],
      (const float*)d_in[5],  (const float*)d_in[7],  (const float*)d_in[9],
      (const float*)d_in[17], (const float*)d_in[19], (const float*)d_in[21],
      (const float*)d_in[15]);

  int B = in_sizes[0] / 100;

  PM pm;
  pm.tokens = (const float*)d_in[0];
  pm.ent_b2 = (const float*)d_in[4];
  pm.pad_b2 = (const float*)d_in[14];
  pm.out = (float*)d_out;
  cudaFuncSetAttribute(spectral_mma_kernel, cudaFuncAttributeMaxDynamicSharedMemorySize, SMEM_SZ);
  dim3 grid(B / 64, 18);
  spectral_mma_kernel<<<grid, NTH, SMEM_SZ>>>(pm);

  PE pe;
  pe.tokens = (const float*)d_in[0];
  pe.ent_bpos = (const float*)d_in[6];
  pe.ent_bc = (const float*)d_in[8];
  pe.ent_bv = (const float*)d_in[10];
  pe.b_bpos = (const float*)d_in[18];
  pe.b_bc = (const float*)d_in[20];
  pe.b_bv = (const float*)d_in[22];
  pe.gs_W = (const float*)d_in[23];
  pe.gs_b = (const float*)d_in[24];
  pe.out = (float*)d_out;
  epilogue_kernel<<<(B + 127) / 128, 128>>>(pe, B);
}